// round 1
// baseline (speedup 1.0000x reference)
#include <cuda_runtime.h>
#include <math.h>

#define SEQLEN 2048
#define DIM    4096
#define NH     32
#define HD     128
#define NKV    8
#define QKV_N  6144          // (32 + 2*8) * 128
#define KV_ROW 1024          // NKV * HD
#define WIN    4096
#define SCALE  0.08838834764831845f  // 128^-0.5

// ---------------- scratch (device globals; no allocation allowed) ----------
__device__ float g_xqkv[SEQLEN * QKV_N];        // 50.3 MB
__device__ float g_q   [SEQLEN * NH * HD];      // 33.5 MB (scaled, post-RoPE)
__device__ float g_attn[SEQLEN * NH * HD];      // 33.5 MB

// ---------------- SGEMM: C[M,N] = A[M,K] * B[N,K]^T  (row-major, K contig) --
__global__ __launch_bounds__(256) void sgemm_abt(
    const float* __restrict__ A, const float* __restrict__ B,
    float* __restrict__ C, int M, int N, int K)
{
    __shared__ float As[16][132];
    __shared__ float Bs[16][132];

    const int tid = threadIdx.x;
    const int lr  = tid >> 2;        // 0..63  (load row)
    const int lc  = tid & 3;         // 0..3   (float4 col within 16-wide k tile)
    const int tx  = tid & 15;        // compute tile x
    const int ty  = tid >> 4;        // compute tile y

    const float* Ab = A + (size_t)blockIdx.y * 128 * K;
    const float* Bb = B + (size_t)blockIdx.x * 128 * K;

    float acc[8][8];
#pragma unroll
    for (int i = 0; i < 8; i++)
#pragma unroll
        for (int j = 0; j < 8; j++) acc[i][j] = 0.f;

    for (int k0 = 0; k0 < K; k0 += 16) {
        float4 a0 = *(const float4*)(Ab + (size_t)lr        * K + k0 + lc * 4);
        float4 a1 = *(const float4*)(Ab + (size_t)(lr + 64) * K + k0 + lc * 4);
        float4 b0 = *(const float4*)(Bb + (size_t)lr        * K + k0 + lc * 4);
        float4 b1 = *(const float4*)(Bb + (size_t)(lr + 64) * K + k0 + lc * 4);

        __syncthreads();
        As[lc*4+0][lr]      = a0.x; As[lc*4+1][lr]      = a0.y;
        As[lc*4+2][lr]      = a0.z; As[lc*4+3][lr]      = a0.w;
        As[lc*4+0][lr+64]   = a1.x; As[lc*4+1][lr+64]   = a1.y;
        As[lc*4+2][lr+64]   = a1.z; As[lc*4+3][lr+64]   = a1.w;
        Bs[lc*4+0][lr]      = b0.x; Bs[lc*4+1][lr]      = b0.y;
        Bs[lc*4+2][lr]      = b0.z; Bs[lc*4+3][lr]      = b0.w;
        Bs[lc*4+0][lr+64]   = b1.x; Bs[lc*4+1][lr+64]   = b1.y;
        Bs[lc*4+2][lr+64]   = b1.z; Bs[lc*4+3][lr+64]   = b1.w;
        __syncthreads();

#pragma unroll
        for (int kk = 0; kk < 16; kk++) {
            float rm[8], rn[8];
            *(float4*)(rm)     = *(const float4*)&As[kk][ty * 8];
            *(float4*)(rm + 4) = *(const float4*)&As[kk][ty * 8 + 4];
            *(float4*)(rn)     = *(const float4*)&Bs[kk][tx * 8];
            *(float4*)(rn + 4) = *(const float4*)&Bs[kk][tx * 8 + 4];
#pragma unroll
            for (int i = 0; i < 8; i++)
#pragma unroll
                for (int j = 0; j < 8; j++)
                    acc[i][j] += rm[i] * rn[j];
        }
    }

#pragma unroll
    for (int i = 0; i < 8; i++) {
        size_t row = (size_t)blockIdx.y * 128 + ty * 8 + i;
        float* cp = C + row * N + (size_t)blockIdx.x * 128 + tx * 8;
        *(float4*)(cp)     = make_float4(acc[i][0], acc[i][1], acc[i][2], acc[i][3]);
        *(float4*)(cp + 4) = make_float4(acc[i][4], acc[i][5], acc[i][6], acc[i][7]);
    }
}

// ---------------- RoPE + scale-fold + cache write ---------------------------
// xqkv row layout: [0,4096) q | [4096,5120) k | [5120,6144) v
__global__ __launch_bounds__(256) void rope_kernel(
    const float* __restrict__ xqkv,
    const float* __restrict__ cosf_, const float* __restrict__ sinf_,
    float* __restrict__ qout, float* __restrict__ kcache, float* __restrict__ vcache)
{
    const int s   = blockIdx.x;
    const int tid = threadIdx.x;
    const float* row = xqkv + (size_t)s * QKV_N;

    // Q: 32 heads * 64 freq pairs = 2048 pairs; fold SCALE in.
    for (int p = tid; p < NH * 64; p += 256) {
        int h = p >> 6, f = p & 63;
        float c  = cosf_[s * 64 + f];
        float sn = sinf_[s * 64 + f];
        float x1 = row[h * HD + 2 * f];
        float x2 = row[h * HD + 2 * f + 1];
        qout[(size_t)s * (NH * HD) + h * HD + 2 * f]     = (x1 * c - x2 * sn) * SCALE;
        qout[(size_t)s * (NH * HD) + h * HD + 2 * f + 1] = (x1 * sn + x2 * c) * SCALE;
    }
    // K: 8 heads * 64 pairs -> cache_k[s][h][d]
    for (int p = tid; p < NKV * 64; p += 256) {
        int h = p >> 6, f = p & 63;
        float c  = cosf_[s * 64 + f];
        float sn = sinf_[s * 64 + f];
        float x1 = row[DIM + h * HD + 2 * f];
        float x2 = row[DIM + h * HD + 2 * f + 1];
        kcache[(size_t)s * KV_ROW + h * HD + 2 * f]     = x1 * c - x2 * sn;
        kcache[(size_t)s * KV_ROW + h * HD + 2 * f + 1] = x1 * sn + x2 * c;
    }
    // V: straight copy
    for (int i = tid; i < KV_ROW; i += 256)
        vcache[(size_t)s * KV_ROW + i] = row[DIM + NKV * HD + i];
}

// ---------------- causal flash attention (fp32) -----------------------------
// grid (32 qtiles, 32 heads), 256 threads. Q tile 64 rows, K/V blocks of 64.
#define SM_STRIDE 132
#define PS_STRIDE 68
#define ATTN_SMEM ((3 * 64 * SM_STRIDE + 64 * PS_STRIDE) * 4)

__global__ __launch_bounds__(256) void attn_kernel(
    const float* __restrict__ Q, const float* __restrict__ Kc,
    const float* __restrict__ Vc, float* __restrict__ O)
{
    extern __shared__ float sm[];
    float* Qs = sm;
    float* Ks = sm + 64 * SM_STRIDE;
    float* Vs = sm + 2 * 64 * SM_STRIDE;
    float* Ps = sm + 3 * 64 * SM_STRIDE;

    const int qt  = blockIdx.x;
    const int h   = blockIdx.y;
    const int kvh = h >> 2;
    const int tid = threadIdx.x;
    const int r   = tid >> 2;     // q row within tile (0..63)
    const int g   = tid & 3;      // column group

    // load Q tile (64 x 128)
    for (int i = tid; i < 64 * 32; i += 256) {
        int row = i >> 5, c4 = (i & 31) * 4;
        *(float4*)&Qs[row * SM_STRIDE + c4] =
            *(const float4*)&Q[(size_t)(qt * 64 + row) * (NH * HD) + h * HD + c4];
    }

    float m = -1e30f, l = 0.f;
    float acc[32];
#pragma unroll
    for (int i = 0; i < 32; i++) acc[i] = 0.f;

    const int qrow = qt * 64 + r;

    for (int kb = 0; kb <= qt; kb++) {
        __syncthreads();   // previous Ks/Vs/Ps consumers done
        for (int i = tid; i < 64 * 32; i += 256) {
            int row = i >> 5, c4 = (i & 31) * 4;
            size_t ga = (size_t)(kb * 64 + row) * KV_ROW + kvh * HD + c4;
            *(float4*)&Ks[row * SM_STRIDE + c4] = *(const float4*)&Kc[ga];
            *(float4*)&Vs[row * SM_STRIDE + c4] = *(const float4*)&Vc[ga];
        }
        __syncthreads();

        // scores for 16 cols: j = jj*4 + g  (conflict-free Ks reads)
        float sc[16];
#pragma unroll
        for (int jj = 0; jj < 16; jj++) sc[jj] = 0.f;
#pragma unroll 4
        for (int d4 = 0; d4 < 32; d4++) {
            float4 qv = *(const float4*)&Qs[r * SM_STRIDE + d4 * 4];
#pragma unroll
            for (int jj = 0; jj < 16; jj++) {
                float4 kv = *(const float4*)&Ks[(jj * 4 + g) * SM_STRIDE + d4 * 4];
                sc[jj] += qv.x * kv.x;
                sc[jj] += qv.y * kv.y;
                sc[jj] += qv.z * kv.z;
                sc[jj] += qv.w * kv.w;
            }
        }
        if (kb == qt) {
#pragma unroll
            for (int jj = 0; jj < 16; jj++)
                if (kb * 64 + jj * 4 + g > qrow) sc[jj] = -1e30f;
        }

        // online softmax over this 64-col block (quad owns a row)
        float mloc = sc[0];
#pragma unroll
        for (int jj = 1; jj < 16; jj++) mloc = fmaxf(mloc, sc[jj]);
        mloc = fmaxf(mloc, __shfl_xor_sync(0xffffffffu, mloc, 1));
        mloc = fmaxf(mloc, __shfl_xor_sync(0xffffffffu, mloc, 2));
        float mnew  = fmaxf(m, mloc);
        float alpha = __expf(m - mnew);
        float lloc  = 0.f;
#pragma unroll
        for (int jj = 0; jj < 16; jj++) {
            float p = __expf(sc[jj] - mnew);
            Ps[r * PS_STRIDE + jj * 4 + g] = p;
            lloc += p;
        }
        lloc += __shfl_xor_sync(0xffffffffu, lloc, 1);
        lloc += __shfl_xor_sync(0xffffffffu, lloc, 2);
        l = l * alpha + lloc;
        m = mnew;
#pragma unroll
        for (int i = 0; i < 32; i++) acc[i] *= alpha;
        __syncwarp();

        // O += P @ V ; thread's cols c = g*4 + i*16 (conflict-free Vs reads)
        for (int j = 0; j < 64; j++) {
            float p = Ps[r * PS_STRIDE + j];
#pragma unroll
            for (int i = 0; i < 8; i++) {
                float4 vv = *(const float4*)&Vs[j * SM_STRIDE + g * 4 + i * 16];
                acc[i * 4 + 0] += p * vv.x;
                acc[i * 4 + 1] += p * vv.y;
                acc[i * 4 + 2] += p * vv.z;
                acc[i * 4 + 3] += p * vv.w;
            }
        }
    }

    float linv = 1.f / l;
#pragma unroll
    for (int i = 0; i < 8; i++) {
        float4 o = make_float4(acc[i*4+0]*linv, acc[i*4+1]*linv,
                               acc[i*4+2]*linv, acc[i*4+3]*linv);
        *(float4*)&O[(size_t)qrow * (NH * HD) + h * HD + g * 4 + i * 16] = o;
    }
}

// ---------------- launch ----------------------------------------------------
extern "C" void kernel_launch(void* const* d_in, const int* in_sizes, int n_in,
                              void* d_out, int out_size)
{
    const float* x     = (const float*)d_in[0];
    const float* cosf_ = (const float*)d_in[1];
    const float* sinf_ = (const float*)d_in[2];
    // d_in[3] positions (identity), d_in[4] mask (implicit causal) unused
    const float* in_ck = (const float*)d_in[5];
    const float* in_cv = (const float*)d_in[6];
    const float* Wqkv  = (const float*)d_in[7];
    const float* Wo    = (const float*)d_in[8];

    float* out     = (float*)d_out;                       // 2048*4096
    float* cache_k = out + (size_t)SEQLEN * DIM;          // 4096*8*128
    float* cache_v = cache_k + (size_t)WIN * KV_ROW;

    float *xqkv_p, *q_p, *attn_p;
    cudaGetSymbolAddress((void**)&xqkv_p, g_xqkv);
    cudaGetSymbolAddress((void**)&q_p,    g_q);
    cudaGetSymbolAddress((void**)&attn_p, g_attn);

    // carry input caches through (rows >= 2048 keep their input values)
    size_t cache_bytes = (size_t)WIN * KV_ROW * sizeof(float);
    cudaMemcpyAsync(cache_k, in_ck, cache_bytes, cudaMemcpyDeviceToDevice, 0);
    cudaMemcpyAsync(cache_v, in_cv, cache_bytes, cudaMemcpyDeviceToDevice, 0);

    // 1) QKV projection: [2048,6144] = x[2048,4096] @ Wqkv[6144,4096]^T
    sgemm_abt<<<dim3(QKV_N / 128, SEQLEN / 128), 256>>>(x, Wqkv, xqkv_p,
                                                        SEQLEN, QKV_N, DIM);
    // 2) RoPE (scale folded into q) + cache writes
    rope_kernel<<<SEQLEN, 256>>>(xqkv_p, cosf_, sinf_, q_p, cache_k, cache_v);

    // 3) causal flash attention
    cudaFuncSetAttribute(attn_kernel, cudaFuncAttributeMaxDynamicSharedMemorySize,
                         ATTN_SMEM);
    attn_kernel<<<dim3(SEQLEN / 64, NH), 256, ATTN_SMEM>>>(q_p, cache_k, cache_v,
                                                           attn_p);

    // 4) output projection: [2048,4096] = attn[2048,4096] @ Wo[4096,4096]^T
    sgemm_abt<<<dim3(DIM / 128, SEQLEN / 128), 256>>>(attn_p, Wo, out,
                                                      SEQLEN, DIM, DIM);
}

// round 3
// speedup vs baseline: 1.4782x; 1.4782x over previous
#include <cuda_runtime.h>
#include <cuda_bf16.h>
#include <cstdint>
#include <math.h>

#define SEQLEN 2048
#define DIM    4096
#define NH     32
#define HD     128
#define NKV    8
#define QKV_N  6144
#define KV_ROW 1024
#define WIN    4096
#define SCALE  0.08838834764831845f
#define K3     12288            // 3 * 4096 (split-bf16 tripled K)

// ---------------- scratch (device globals; no allocation allowed) ----------
__device__ float g_xqkv[SEQLEN * QKV_N];
__device__ float g_q   [SEQLEN * NH * HD];
__device__ float g_attn[SEQLEN * NH * HD];
__device__ __nv_bfloat16 g_xc   [(size_t)SEQLEN * K3];
__device__ __nv_bfloat16 g_attnc[(size_t)SEQLEN * K3];
__device__ __nv_bfloat16 g_wqkvc[(size_t)QKV_N * K3];
__device__ __nv_bfloat16 g_woc  [(size_t)DIM * K3];

// ---------------- fp32 -> split-bf16 conversion ----------------------------
// A (activations): segs [hi | lo | hi];  B (weights): segs [hi | hi | lo]
// A'.B'^T = Ah.Bh + Al.Bh + Ah.Bl ~= fp32 A.B (drops only Al.Bl ~ 2^-16)
__global__ __launch_bounds__(256) void convert_split(
    const float* __restrict__ in, __nv_bfloat16* __restrict__ out,
    int K, int isA, long long total4)
{
    long long i = (long long)blockIdx.x * 256 + threadIdx.x;
    if (i >= total4) return;
    int k4 = K >> 2;
    long long row = i / k4;
    int c = (int)(i - row * k4);
    float4 v = ((const float4*)in)[i];
    float vv[4] = {v.x, v.y, v.z, v.w};
    union { unsigned long long u; __nv_bfloat16 h[4]; } hi, lo;
#pragma unroll
    for (int j = 0; j < 4; j++) {
        __nv_bfloat16 h = __float2bfloat16(vv[j]);
        hi.h[j] = h;
        lo.h[j] = __float2bfloat16(vv[j] - __bfloat162float(h));
    }
    size_t base = (size_t)row * (3 * K) + (size_t)c * 4;
    *(unsigned long long*)(out + base)         = hi.u;
    *(unsigned long long*)(out + base + K)     = isA ? lo.u : hi.u;
    *(unsigned long long*)(out + base + 2 * K) = isA ? hi.u : lo.u;
}

// ---------------- mma.sync bf16 GEMM: C[M,N] = A'[M,K3] * B'[N,K3]^T -------
#define KC       32
#define NCHUNK   (K3 / KC)           // 384
#define RSTRIDE  80                  // smem row stride bytes (64B data + 16 pad)
#define TILEB    (128 * RSTRIDE)     // 10240 bytes per operand tile
#define STAGEB   (2 * TILEB)         // 20480
#define GSTAGES  4
#define GEMM_SMEM (GSTAGES * STAGEB) // 81920

__device__ __forceinline__ void cp16(uint32_t d, const void* g) {
    asm volatile("cp.async.cg.shared.global [%0], [%1], 16;\n"
                 :: "r"(d), "l"(__cvta_generic_to_global(g)) : "memory");
}
__device__ __forceinline__ void ldm4(uint32_t& r0, uint32_t& r1,
                                     uint32_t& r2, uint32_t& r3, uint32_t a) {
    asm volatile("ldmatrix.sync.aligned.m8n8.x4.shared.b16 {%0,%1,%2,%3}, [%4];"
                 : "=r"(r0), "=r"(r1), "=r"(r2), "=r"(r3) : "r"(a));
}
__device__ __forceinline__ void mma16816(float* c, const uint32_t* a,
                                         const uint32_t* b) {
    asm volatile(
        "mma.sync.aligned.m16n8k16.row.col.f32.bf16.bf16.f32 "
        "{%0,%1,%2,%3}, {%4,%5,%6,%7}, {%8,%9}, {%0,%1,%2,%3};"
        : "+f"(c[0]), "+f"(c[1]), "+f"(c[2]), "+f"(c[3])
        : "r"(a[0]), "r"(a[1]), "r"(a[2]), "r"(a[3]), "r"(b[0]), "r"(b[1]));
}

__global__ __launch_bounds__(256) void gemm_mma(
    const __nv_bfloat16* __restrict__ A, const __nv_bfloat16* __restrict__ B,
    float* __restrict__ C, int N)
{
    extern __shared__ __align__(128) char smraw[];
    const uint32_t sb = (uint32_t)__cvta_generic_to_shared(smraw);

    const int tid = threadIdx.x;
    const int w   = tid >> 5;
    const int l   = tid & 31;
    const int wm  = w & 1;          // 0-1 : 64-row slab
    const int wn  = w >> 1;         // 0-3 : 32-col slab

    const char* Ab = (const char*)(A + (size_t)blockIdx.y * 128 * K3);
    const char* Bb = (const char*)(B + (size_t)blockIdx.x * 128 * K3);

    // --- global->smem slots: 512 x 16B per operand, 2 per thread each ------
    const int r0 = tid >> 2,        s0 = (tid & 3) * 16;          // slot tid
    const int r1 = (tid + 256) >> 2, s1 = ((tid + 256) & 3) * 16; // slot tid+256

    auto load_chunk = [&](int t, int stg) {
        const size_t gk = (size_t)t * 64;   // byte offset along K
        uint32_t sa = sb + stg * STAGEB;
        uint32_t sbB = sa + TILEB;
        cp16(sa  + r0 * RSTRIDE + s0, Ab + (size_t)r0 * (K3 * 2) + gk + s0);
        cp16(sa  + r1 * RSTRIDE + s1, Ab + (size_t)r1 * (K3 * 2) + gk + s1);
        cp16(sbB + r0 * RSTRIDE + s0, Bb + (size_t)r0 * (K3 * 2) + gk + s0);
        cp16(sbB + r1 * RSTRIDE + s1, Bb + (size_t)r1 * (K3 * 2) + gk + s1);
    };

    // --- ldmatrix per-lane offsets -----------------------------------------
    // A x4: rows (l&15), k-half (l>>4)
    const uint32_t aoff = (uint32_t)((wm * 64 + (l & 15)) * RSTRIDE + (l >> 4) * 16);
    // B x4: row 8*(sel>>1)+l2, k-half (sel&1)
    const int l2 = l & 7, sel = l >> 3;
    const uint32_t boff = (uint32_t)(TILEB + (wn * 32 + (sel >> 1) * 8 + l2) * RSTRIDE
                                     + (sel & 1) * 16);

    float acc[4][4][4];
#pragma unroll
    for (int mt = 0; mt < 4; mt++)
#pragma unroll
        for (int nt = 0; nt < 4; nt++)
#pragma unroll
            for (int i = 0; i < 4; i++) acc[mt][nt][i] = 0.f;

    // prefill 3 chunks
    for (int t = 0; t < GSTAGES - 1; t++) {
        load_chunk(t, t);
        asm volatile("cp.async.commit_group;" ::: "memory");
    }

    for (int k = 0; k < NCHUNK; k++) {
        asm volatile("cp.async.wait_group 2;" ::: "memory");
        __syncthreads();

        int t = k + GSTAGES - 1;
        if (t < NCHUNK) load_chunk(t, t & (GSTAGES - 1));
        asm volatile("cp.async.commit_group;" ::: "memory");

        const uint32_t stage = sb + (k & (GSTAGES - 1)) * STAGEB;
#pragma unroll
        for (int ks = 0; ks < 2; ks++) {
            uint32_t a[4][4], b[4][2];
#pragma unroll
            for (int mt = 0; mt < 4; mt++)
                ldm4(a[mt][0], a[mt][1], a[mt][2], a[mt][3],
                     stage + aoff + mt * (16 * RSTRIDE) + ks * 32);
#pragma unroll
            for (int np = 0; np < 2; np++)
                ldm4(b[2*np][0], b[2*np][1], b[2*np+1][0], b[2*np+1][1],
                     stage + boff + np * (16 * RSTRIDE) + ks * 32);
#pragma unroll
            for (int mt = 0; mt < 4; mt++)
#pragma unroll
                for (int nt = 0; nt < 4; nt++)
                    mma16816(acc[mt][nt], a[mt], b[nt]);
        }
    }

    // --- epilogue -----------------------------------------------------------
    const int crow = blockIdx.y * 128 + wm * 64 + (l >> 2);
    const int ccol = blockIdx.x * 128 + wn * 32 + (l & 3) * 2;
#pragma unroll
    for (int mt = 0; mt < 4; mt++) {
#pragma unroll
        for (int nt = 0; nt < 4; nt++) {
            float* p0 = C + (size_t)(crow + mt * 16)     * N + ccol + nt * 8;
            float* p1 = C + (size_t)(crow + mt * 16 + 8) * N + ccol + nt * 8;
            *(float2*)p0 = make_float2(acc[mt][nt][0], acc[mt][nt][1]);
            *(float2*)p1 = make_float2(acc[mt][nt][2], acc[mt][nt][3]);
        }
    }
}

// ---------------- RoPE + scale-fold + cache write ---------------------------
__global__ __launch_bounds__(256) void rope_kernel(
    const float* __restrict__ xqkv,
    const float* __restrict__ cosf_, const float* __restrict__ sinf_,
    float* __restrict__ qout, float* __restrict__ kcache, float* __restrict__ vcache)
{
    const int s   = blockIdx.x;
    const int tid = threadIdx.x;
    const float* row = xqkv + (size_t)s * QKV_N;

    for (int p = tid; p < NH * 64; p += 256) {
        int h = p >> 6, f = p & 63;
        float c  = cosf_[s * 64 + f];
        float sn = sinf_[s * 64 + f];
        float x1 = row[h * HD + 2 * f];
        float x2 = row[h * HD + 2 * f + 1];
        qout[(size_t)s * (NH * HD) + h * HD + 2 * f]     = (x1 * c - x2 * sn) * SCALE;
        qout[(size_t)s * (NH * HD) + h * HD + 2 * f + 1] = (x1 * sn + x2 * c) * SCALE;
    }
    for (int p = tid; p < NKV * 64; p += 256) {
        int h = p >> 6, f = p & 63;
        float c  = cosf_[s * 64 + f];
        float sn = sinf_[s * 64 + f];
        float x1 = row[DIM + h * HD + 2 * f];
        float x2 = row[DIM + h * HD + 2 * f + 1];
        kcache[(size_t)s * KV_ROW + h * HD + 2 * f]     = x1 * c - x2 * sn;
        kcache[(size_t)s * KV_ROW + h * HD + 2 * f + 1] = x1 * sn + x2 * c;
    }
    for (int i = tid; i < KV_ROW; i += 256)
        vcache[(size_t)s * KV_ROW + i] = row[DIM + NKV * HD + i];
}

// ---------------- causal flash attention (fp32) -----------------------------
#define SM_STRIDE 132
#define PS_STRIDE 68
#define ATTN_SMEM ((3 * 64 * SM_STRIDE + 64 * PS_STRIDE) * 4)

__global__ __launch_bounds__(256) void attn_kernel(
    const float* __restrict__ Q, const float* __restrict__ Kc,
    const float* __restrict__ Vc, float* __restrict__ O)
{
    extern __shared__ float sm[];
    float* Qs = sm;
    float* Ks = sm + 64 * SM_STRIDE;
    float* Vs = sm + 2 * 64 * SM_STRIDE;
    float* Ps = sm + 3 * 64 * SM_STRIDE;

    const int qt  = blockIdx.x;
    const int h   = blockIdx.y;
    const int kvh = h >> 2;
    const int tid = threadIdx.x;
    const int r   = tid >> 2;
    const int g   = tid & 3;

    for (int i = tid; i < 64 * 32; i += 256) {
        int row = i >> 5, c4 = (i & 31) * 4;
        *(float4*)&Qs[row * SM_STRIDE + c4] =
            *(const float4*)&Q[(size_t)(qt * 64 + row) * (NH * HD) + h * HD + c4];
    }

    float m = -1e30f, l = 0.f;
    float acc[32];
#pragma unroll
    for (int i = 0; i < 32; i++) acc[i] = 0.f;

    const int qrow = qt * 64 + r;

    for (int kb = 0; kb <= qt; kb++) {
        __syncthreads();
        for (int i = tid; i < 64 * 32; i += 256) {
            int row = i >> 5, c4 = (i & 31) * 4;
            size_t ga = (size_t)(kb * 64 + row) * KV_ROW + kvh * HD + c4;
            *(float4*)&Ks[row * SM_STRIDE + c4] = *(const float4*)&Kc[ga];
            *(float4*)&Vs[row * SM_STRIDE + c4] = *(const float4*)&Vc[ga];
        }
        __syncthreads();

        float sc[16];
#pragma unroll
        for (int jj = 0; jj < 16; jj++) sc[jj] = 0.f;
#pragma unroll 4
        for (int d4 = 0; d4 < 32; d4++) {
            float4 qv = *(const float4*)&Qs[r * SM_STRIDE + d4 * 4];
#pragma unroll
            for (int jj = 0; jj < 16; jj++) {
                float4 kv = *(const float4*)&Ks[(jj * 4 + g) * SM_STRIDE + d4 * 4];
                sc[jj] += qv.x * kv.x;
                sc[jj] += qv.y * kv.y;
                sc[jj] += qv.z * kv.z;
                sc[jj] += qv.w * kv.w;
            }
        }
        if (kb == qt) {
#pragma unroll
            for (int jj = 0; jj < 16; jj++)
                if (kb * 64 + jj * 4 + g > qrow) sc[jj] = -1e30f;
        }

        float mloc = sc[0];
#pragma unroll
        for (int jj = 1; jj < 16; jj++) mloc = fmaxf(mloc, sc[jj]);
        mloc = fmaxf(mloc, __shfl_xor_sync(0xffffffffu, mloc, 1));
        mloc = fmaxf(mloc, __shfl_xor_sync(0xffffffffu, mloc, 2));
        float mnew  = fmaxf(m, mloc);
        float alpha = __expf(m - mnew);
        float lloc  = 0.f;
#pragma unroll
        for (int jj = 0; jj < 16; jj++) {
            float p = __expf(sc[jj] - mnew);
            Ps[r * PS_STRIDE + jj * 4 + g] = p;
            lloc += p;
        }
        lloc += __shfl_xor_sync(0xffffffffu, lloc, 1);
        lloc += __shfl_xor_sync(0xffffffffu, lloc, 2);
        l = l * alpha + lloc;
        m = mnew;
#pragma unroll
        for (int i = 0; i < 32; i++) acc[i] *= alpha;
        __syncwarp();

        for (int j = 0; j < 64; j++) {
            float p = Ps[r * PS_STRIDE + j];
#pragma unroll
            for (int i = 0; i < 8; i++) {
                float4 vv = *(const float4*)&Vs[j * SM_STRIDE + g * 4 + i * 16];
                acc[i * 4 + 0] += p * vv.x;
                acc[i * 4 + 1] += p * vv.y;
                acc[i * 4 + 2] += p * vv.z;
                acc[i * 4 + 3] += p * vv.w;
            }
        }
    }

    float linv = 1.f / l;
#pragma unroll
    for (int i = 0; i < 8; i++) {
        float4 o = make_float4(acc[i*4+0]*linv, acc[i*4+1]*linv,
                               acc[i*4+2]*linv, acc[i*4+3]*linv);
        *(float4*)&O[(size_t)qrow * (NH * HD) + h * HD + g * 4 + i * 16] = o;
    }
}

// ---------------- launch ----------------------------------------------------
extern "C" void kernel_launch(void* const* d_in, const int* in_sizes, int n_in,
                              void* d_out, int out_size)
{
    const float* x     = (const float*)d_in[0];
    const float* cosf_ = (const float*)d_in[1];
    const float* sinf_ = (const float*)d_in[2];
    const float* in_ck = (const float*)d_in[5];
    const float* in_cv = (const float*)d_in[6];
    const float* Wqkv  = (const float*)d_in[7];
    const float* Wo    = (const float*)d_in[8];

    float* out     = (float*)d_out;
    float* cache_k = out + (size_t)SEQLEN * DIM;
    float* cache_v = cache_k + (size_t)WIN * KV_ROW;

    float *xqkv_p, *q_p, *attn_p;
    __nv_bfloat16 *xc_p, *attnc_p, *wqkvc_p, *woc_p;
    cudaGetSymbolAddress((void**)&xqkv_p,  g_xqkv);
    cudaGetSymbolAddress((void**)&q_p,     g_q);
    cudaGetSymbolAddress((void**)&attn_p,  g_attn);
    cudaGetSymbolAddress((void**)&xc_p,    g_xc);
    cudaGetSymbolAddress((void**)&attnc_p, g_attnc);
    cudaGetSymbolAddress((void**)&wqkvc_p, g_wqkvc);
    cudaGetSymbolAddress((void**)&woc_p,   g_woc);

    size_t cache_bytes = (size_t)WIN * KV_ROW * sizeof(float);
    cudaMemcpyAsync(cache_k, in_ck, cache_bytes, cudaMemcpyDeviceToDevice, 0);
    cudaMemcpyAsync(cache_v, in_cv, cache_bytes, cudaMemcpyDeviceToDevice, 0);

    cudaFuncSetAttribute(gemm_mma, cudaFuncAttributeMaxDynamicSharedMemorySize,
                         GEMM_SMEM);
    cudaFuncSetAttribute(attn_kernel, cudaFuncAttributeMaxDynamicSharedMemorySize,
                         ATTN_SMEM);

    // split-bf16 conversions
    {
        long long t4;
        t4 = (long long)SEQLEN * DIM / 4;
        convert_split<<<(unsigned)((t4 + 255) / 256), 256>>>(x, xc_p, DIM, 1, t4);
        t4 = (long long)QKV_N * DIM / 4;
        convert_split<<<(unsigned)((t4 + 255) / 256), 256>>>(Wqkv, wqkvc_p, DIM, 0, t4);
        t4 = (long long)DIM * DIM / 4;
        convert_split<<<(unsigned)((t4 + 255) / 256), 256>>>(Wo, woc_p, DIM, 0, t4);
    }

    // 1) QKV projection on tensor cores (mma.sync bf16, split-K3)
    gemm_mma<<<dim3(QKV_N / 128, SEQLEN / 128), 256, GEMM_SMEM>>>(
        xc_p, wqkvc_p, xqkv_p, QKV_N);

    // 2) RoPE + cache writes
    rope_kernel<<<SEQLEN, 256>>>(xqkv_p, cosf_, sinf_, q_p, cache_k, cache_v);

    // 3) causal flash attention (fp32)
    attn_kernel<<<dim3(SEQLEN / 64, NH), 256, ATTN_SMEM>>>(q_p, cache_k, cache_v,
                                                           attn_p);

    // 4) output projection on tensor cores
    {
        long long t4 = (long long)SEQLEN * DIM / 4;
        convert_split<<<(unsigned)((t4 + 255) / 256), 256>>>(attn_p, attnc_p, DIM, 1, t4);
    }
    gemm_mma<<<dim3(DIM / 128, SEQLEN / 128), 256, GEMM_SMEM>>>(
        attnc_p, woc_p, out, DIM);
}

// round 4
// speedup vs baseline: 2.8504x; 1.9283x over previous
#include <cuda_runtime.h>
#include <cuda_bf16.h>
#include <cstdint>
#include <math.h>

#define SEQLEN 2048
#define DIM    4096
#define NH     32
#define HD     128
#define NKV    8
#define QKV_N  6144
#define KV_ROW 1024
#define WIN    4096
#define SCALE  0.08838834764831845f
#define K3     12288

// ---------------- scratch (device globals) ----------------------------------
__device__ float g_xqkv[SEQLEN * QKV_N];
__device__ float g_q   [SEQLEN * NH * HD];
__device__ float g_attn[SEQLEN * NH * HD];
__device__ __nv_bfloat16 g_xc   [(size_t)SEQLEN * K3];
__device__ __nv_bfloat16 g_attnc[(size_t)SEQLEN * K3];
__device__ __nv_bfloat16 g_wqkvc[(size_t)QKV_N * K3];
__device__ __nv_bfloat16 g_woc  [(size_t)DIM * K3];
// split q/k/v for tensorized attention: [head][seq][HD]
__device__ __nv_bfloat16 g_qhi[(size_t)NH  * SEQLEN * HD];
__device__ __nv_bfloat16 g_qlo[(size_t)NH  * SEQLEN * HD];
__device__ __nv_bfloat16 g_khi[(size_t)NKV * SEQLEN * HD];
__device__ __nv_bfloat16 g_klo[(size_t)NKV * SEQLEN * HD];
__device__ __nv_bfloat16 g_vhi[(size_t)NKV * SEQLEN * HD];
__device__ __nv_bfloat16 g_vlo[(size_t)NKV * SEQLEN * HD];

// ---------------- common PTX helpers ----------------------------------------
__device__ __forceinline__ void cp16(uint32_t d, const void* g) {
    asm volatile("cp.async.cg.shared.global [%0], [%1], 16;\n"
                 :: "r"(d), "l"(__cvta_generic_to_global(g)) : "memory");
}
__device__ __forceinline__ void ldm4(uint32_t& r0, uint32_t& r1,
                                     uint32_t& r2, uint32_t& r3, uint32_t a) {
    asm volatile("ldmatrix.sync.aligned.m8n8.x4.shared.b16 {%0,%1,%2,%3}, [%4];"
                 : "=r"(r0), "=r"(r1), "=r"(r2), "=r"(r3) : "r"(a));
}
__device__ __forceinline__ void ldm4t(uint32_t& r0, uint32_t& r1,
                                      uint32_t& r2, uint32_t& r3, uint32_t a) {
    asm volatile("ldmatrix.sync.aligned.m8n8.x4.trans.shared.b16 {%0,%1,%2,%3}, [%4];"
                 : "=r"(r0), "=r"(r1), "=r"(r2), "=r"(r3) : "r"(a));
}
__device__ __forceinline__ void mma16816(float* c, const uint32_t* a,
                                         const uint32_t* b) {
    asm volatile(
        "mma.sync.aligned.m16n8k16.row.col.f32.bf16.bf16.f32 "
        "{%0,%1,%2,%3}, {%4,%5,%6,%7}, {%8,%9}, {%0,%1,%2,%3};"
        : "+f"(c[0]), "+f"(c[1]), "+f"(c[2]), "+f"(c[3])
        : "r"(a[0]), "r"(a[1]), "r"(a[2]), "r"(a[3]), "r"(b[0]), "r"(b[1]));
}
__device__ __forceinline__ void split2(float x, float y, uint32_t& hi, uint32_t& lo) {
    __nv_bfloat162 h = __floats2bfloat162_rn(x, y);
    float rx = x - __bfloat162float(h.x);
    float ry = y - __bfloat162float(h.y);
    __nv_bfloat162 r = __floats2bfloat162_rn(rx, ry);
    hi = *(uint32_t*)&h; lo = *(uint32_t*)&r;
}

// ---------------- fp32 -> split-bf16 (tripled-K GEMM operands) --------------
__global__ __launch_bounds__(256) void convert_split(
    const float* __restrict__ in, __nv_bfloat16* __restrict__ out,
    int K, int isA, long long total4)
{
    long long i = (long long)blockIdx.x * 256 + threadIdx.x;
    if (i >= total4) return;
    int k4 = K >> 2;
    long long row = i / k4;
    int c = (int)(i - row * k4);
    float4 v = ((const float4*)in)[i];
    float vv[4] = {v.x, v.y, v.z, v.w};
    union { unsigned long long u; __nv_bfloat16 h[4]; } hi, lo;
#pragma unroll
    for (int j = 0; j < 4; j++) {
        __nv_bfloat16 h = __float2bfloat16(vv[j]);
        hi.h[j] = h;
        lo.h[j] = __float2bfloat16(vv[j] - __bfloat162float(h));
    }
    size_t base = (size_t)row * (3 * K) + (size_t)c * 4;
    *(unsigned long long*)(out + base)         = hi.u;
    *(unsigned long long*)(out + base + K)     = isA ? lo.u : hi.u;
    *(unsigned long long*)(out + base + 2 * K) = isA ? hi.u : lo.u;
}

// ---------------- mma.sync bf16 GEMM (unchanged from R3) --------------------
#define KC       32
#define NCHUNK   (K3 / KC)
#define RSTRIDE  80
#define TILEB    (128 * RSTRIDE)
#define STAGEB   (2 * TILEB)
#define GSTAGES  4
#define GEMM_SMEM (GSTAGES * STAGEB)

__global__ __launch_bounds__(256) void gemm_mma(
    const __nv_bfloat16* __restrict__ A, const __nv_bfloat16* __restrict__ B,
    float* __restrict__ C, int N)
{
    extern __shared__ __align__(128) char smraw[];
    const uint32_t sb = (uint32_t)__cvta_generic_to_shared(smraw);

    const int tid = threadIdx.x;
    const int w   = tid >> 5;
    const int l   = tid & 31;
    const int wm  = w & 1;
    const int wn  = w >> 1;

    const char* Ab = (const char*)(A + (size_t)blockIdx.y * 128 * K3);
    const char* Bb = (const char*)(B + (size_t)blockIdx.x * 128 * K3);

    const int r0 = tid >> 2,         s0 = (tid & 3) * 16;
    const int r1 = (tid + 256) >> 2, s1 = ((tid + 256) & 3) * 16;

    auto load_chunk = [&](int t, int stg) {
        const size_t gk = (size_t)t * 64;
        uint32_t sa = sb + stg * STAGEB;
        uint32_t sbB = sa + TILEB;
        cp16(sa  + r0 * RSTRIDE + s0, Ab + (size_t)r0 * (K3 * 2) + gk + s0);
        cp16(sa  + r1 * RSTRIDE + s1, Ab + (size_t)r1 * (K3 * 2) + gk + s1);
        cp16(sbB + r0 * RSTRIDE + s0, Bb + (size_t)r0 * (K3 * 2) + gk + s0);
        cp16(sbB + r1 * RSTRIDE + s1, Bb + (size_t)r1 * (K3 * 2) + gk + s1);
    };

    const uint32_t aoff = (uint32_t)((wm * 64 + (l & 15)) * RSTRIDE + (l >> 4) * 16);
    const int l2 = l & 7, sel = l >> 3;
    const uint32_t boff = (uint32_t)(TILEB + (wn * 32 + (sel >> 1) * 8 + l2) * RSTRIDE
                                     + (sel & 1) * 16);

    float acc[4][4][4];
#pragma unroll
    for (int mt = 0; mt < 4; mt++)
#pragma unroll
        for (int nt = 0; nt < 4; nt++)
#pragma unroll
            for (int i = 0; i < 4; i++) acc[mt][nt][i] = 0.f;

    for (int t = 0; t < GSTAGES - 1; t++) {
        load_chunk(t, t);
        asm volatile("cp.async.commit_group;" ::: "memory");
    }

    for (int k = 0; k < NCHUNK; k++) {
        asm volatile("cp.async.wait_group 2;" ::: "memory");
        __syncthreads();

        int t = k + GSTAGES - 1;
        if (t < NCHUNK) load_chunk(t, t & (GSTAGES - 1));
        asm volatile("cp.async.commit_group;" ::: "memory");

        const uint32_t stage = sb + (k & (GSTAGES - 1)) * STAGEB;
#pragma unroll
        for (int ks = 0; ks < 2; ks++) {
            uint32_t a[4][4], b[4][2];
#pragma unroll
            for (int mt = 0; mt < 4; mt++)
                ldm4(a[mt][0], a[mt][1], a[mt][2], a[mt][3],
                     stage + aoff + mt * (16 * RSTRIDE) + ks * 32);
#pragma unroll
            for (int np = 0; np < 2; np++)
                ldm4(b[2*np][0], b[2*np][1], b[2*np+1][0], b[2*np+1][1],
                     stage + boff + np * (16 * RSTRIDE) + ks * 32);
#pragma unroll
            for (int mt = 0; mt < 4; mt++)
#pragma unroll
                for (int nt = 0; nt < 4; nt++)
                    mma16816(acc[mt][nt], a[mt], b[nt]);
        }
    }

    const int crow = blockIdx.y * 128 + wm * 64 + (l >> 2);
    const int ccol = blockIdx.x * 128 + wn * 32 + (l & 3) * 2;
#pragma unroll
    for (int mt = 0; mt < 4; mt++) {
#pragma unroll
        for (int nt = 0; nt < 4; nt++) {
            float* p0 = C + (size_t)(crow + mt * 16)     * N + ccol + nt * 8;
            float* p1 = C + (size_t)(crow + mt * 16 + 8) * N + ccol + nt * 8;
            *(float2*)p0 = make_float2(acc[mt][nt][0], acc[mt][nt][1]);
            *(float2*)p1 = make_float2(acc[mt][nt][2], acc[mt][nt][3]);
        }
    }
}

// ---------------- RoPE + scale-fold + cache write ---------------------------
__global__ __launch_bounds__(256) void rope_kernel(
    const float* __restrict__ xqkv,
    const float* __restrict__ cosf_, const float* __restrict__ sinf_,
    float* __restrict__ qout, float* __restrict__ kcache, float* __restrict__ vcache)
{
    const int s   = blockIdx.x;
    const int tid = threadIdx.x;
    const float* row = xqkv + (size_t)s * QKV_N;

    for (int p = tid; p < NH * 64; p += 256) {
        int h = p >> 6, f = p & 63;
        float c  = cosf_[s * 64 + f];
        float sn = sinf_[s * 64 + f];
        float x1 = row[h * HD + 2 * f];
        float x2 = row[h * HD + 2 * f + 1];
        qout[(size_t)s * (NH * HD) + h * HD + 2 * f]     = (x1 * c - x2 * sn) * SCALE;
        qout[(size_t)s * (NH * HD) + h * HD + 2 * f + 1] = (x1 * sn + x2 * c) * SCALE;
    }
    for (int p = tid; p < NKV * 64; p += 256) {
        int h = p >> 6, f = p & 63;
        float c  = cosf_[s * 64 + f];
        float sn = sinf_[s * 64 + f];
        float x1 = row[DIM + h * HD + 2 * f];
        float x2 = row[DIM + h * HD + 2 * f + 1];
        kcache[(size_t)s * KV_ROW + h * HD + 2 * f]     = x1 * c - x2 * sn;
        kcache[(size_t)s * KV_ROW + h * HD + 2 * f + 1] = x1 * sn + x2 * c;
    }
    for (int i = tid; i < KV_ROW; i += 256)
        vcache[(size_t)s * KV_ROW + i] = row[DIM + NKV * HD + i];
}

// ---------------- q / kv split-bf16 prep for attention ----------------------
__global__ __launch_bounds__(256) void qsplit(
    const float* __restrict__ q,
    __nv_bfloat16* __restrict__ qhi, __nv_bfloat16* __restrict__ qlo)
{
    const int s = blockIdx.x, tid = threadIdx.x;
    for (int i = tid; i < NH * HD; i += 256) {
        int h = i >> 7, d = i & 127;
        float v = q[(size_t)s * (NH * HD) + i];
        __nv_bfloat16 hv = __float2bfloat16(v);
        size_t o = ((size_t)h * SEQLEN + s) * HD + d;
        qhi[o] = hv;
        qlo[o] = __float2bfloat16(v - __bfloat162float(hv));
    }
}
__global__ __launch_bounds__(256) void kvsplit(
    const float* __restrict__ kc, const float* __restrict__ vc,
    __nv_bfloat16* __restrict__ khi, __nv_bfloat16* __restrict__ klo,
    __nv_bfloat16* __restrict__ vhi, __nv_bfloat16* __restrict__ vlo)
{
    const int s = blockIdx.x, tid = threadIdx.x;
    for (int i = tid; i < NKV * HD; i += 256) {
        int h = i >> 7, d = i & 127;
        size_t o = ((size_t)h * SEQLEN + s) * HD + d;
        float kv = kc[(size_t)s * KV_ROW + i];
        __nv_bfloat16 kh = __float2bfloat16(kv);
        khi[o] = kh;
        klo[o] = __float2bfloat16(kv - __bfloat162float(kh));
        float vv = vc[(size_t)s * KV_ROW + i];
        __nv_bfloat16 vh = __float2bfloat16(vv);
        vhi[o] = vh;
        vlo[o] = __float2bfloat16(vv - __bfloat162float(vh));
    }
}

// ---------------- tensor-core causal flash attention ------------------------
// CTA: 128 q rows x 1 head, 8 warps x 16 rows. kb blocks of 64 k-rows.
#define ASTRIDE 272                        // 128 bf16 + 8 pad, bytes
#define ATILE   (64 * ASTRIDE)             // 17408 per operand tile
#define ATTN_SMEM (4 * ATILE)              // Khi | Klo | Vhi | Vlo

__global__ __launch_bounds__(256, 1) void attn_tc(
    const __nv_bfloat16* __restrict__ Qh, const __nv_bfloat16* __restrict__ Ql,
    const __nv_bfloat16* __restrict__ Kh, const __nv_bfloat16* __restrict__ Kl,
    const __nv_bfloat16* __restrict__ Vh, const __nv_bfloat16* __restrict__ Vl,
    float* __restrict__ O)
{
    extern __shared__ __align__(128) char smraw[];
    const uint32_t sb = (uint32_t)__cvta_generic_to_shared(smraw);
    const int tid = threadIdx.x, w = tid >> 5, l = tid & 31;
    const int qt  = (int)gridDim.x - 1 - (int)blockIdx.x;   // heavy tiles first
    const int h   = blockIdx.y;
    const int kvh = h >> 2;

    // ---- Q tile (hi, lo) -> registers via smem staging ----------------------
    uint32_t qh_[8][4], ql_[8][4];
    {
        const uint32_t aoff = sb + (uint32_t)((w * 16 + (l & 15)) * ASTRIDE
                                              + (l >> 4) * 16);
        for (int part = 0; part < 2; part++) {
            const __nv_bfloat16* src = part ? Ql : Qh;
            const char* g0 = (const char*)(src + ((size_t)h * SEQLEN + qt * 128) * HD);
            for (int i = tid; i < 2048; i += 256)
                cp16(sb + (uint32_t)((i >> 4) * ASTRIDE + (i & 15) * 16),
                     g0 + (size_t)i * 16);
            asm volatile("cp.async.commit_group;" ::: "memory");
            asm volatile("cp.async.wait_group 0;" ::: "memory");
            __syncthreads();
            uint32_t (*dst)[4] = part ? ql_ : qh_;
#pragma unroll
            for (int g = 0; g < 8; g++)
                ldm4(dst[g][0], dst[g][1], dst[g][2], dst[g][3], aoff + g * 32);
            __syncthreads();
        }
    }

    float o[16][4];
#pragma unroll
    for (int t = 0; t < 16; t++)
#pragma unroll
        for (int i = 0; i < 4; i++) o[t][i] = 0.f;
    float m0 = -1e30f, m1 = -1e30f, l0 = 0.f, l1 = 0.f;

    const int row0 = qt * 128 + w * 16 + (l >> 2);
    const int l2 = l & 7, sel = l >> 3;
    const int nkb = 2 * qt + 2;

    for (int kb = 0; kb < nkb; kb++) {
        // load K/V split tiles (64 x 128 bf16 each)
        {
            const size_t gbase = (((size_t)kvh * SEQLEN + (size_t)kb * 64) * HD) * 2;
            for (int i = tid; i < 1024; i += 256) {
                uint32_t soff = (uint32_t)((i >> 4) * ASTRIDE + (i & 15) * 16);
                size_t goff = gbase + (size_t)i * 16;
                cp16(sb + 0 * ATILE + soff, (const char*)Kh + goff);
                cp16(sb + 1 * ATILE + soff, (const char*)Kl + goff);
                cp16(sb + 2 * ATILE + soff, (const char*)Vh + goff);
                cp16(sb + 3 * ATILE + soff, (const char*)Vl + goff);
            }
            asm volatile("cp.async.commit_group;" ::: "memory");
            asm volatile("cp.async.wait_group 0;" ::: "memory");
            __syncthreads();
        }

        // ---- scores: S = Q K^T (3-term split) ------------------------------
        float sc[8][4];
#pragma unroll
        for (int t = 0; t < 8; t++)
#pragma unroll
            for (int i = 0; i < 4; i++) sc[t][i] = 0.f;

#pragma unroll
        for (int g = 0; g < 8; g++) {
#pragma unroll
            for (int n16 = 0; n16 < 4; n16++) {
                uint32_t kaddr = sb + (uint32_t)((n16 * 16 + (sel >> 1) * 8 + l2)
                                                 * ASTRIDE + (sel & 1) * 16 + g * 32);
                uint32_t bh[2][2], bl[2][2];
                ldm4(bh[0][0], bh[0][1], bh[1][0], bh[1][1], kaddr);
                ldm4(bl[0][0], bl[0][1], bl[1][0], bl[1][1], kaddr + ATILE);
#pragma unroll
                for (int j = 0; j < 2; j++) {
                    int t = n16 * 2 + j;
                    mma16816(sc[t], qh_[g], bh[j]);
                    mma16816(sc[t], ql_[g], bh[j]);
                    mma16816(sc[t], qh_[g], bl[j]);
                }
            }
        }

        // causal mask on diagonal blocks
        if (kb >= 2 * qt) {
#pragma unroll
            for (int t = 0; t < 8; t++) {
                int col = kb * 64 + t * 8 + 2 * (l & 3);
                if (col     > row0)     sc[t][0] = -1e30f;
                if (col + 1 > row0)     sc[t][1] = -1e30f;
                if (col     > row0 + 8) sc[t][2] = -1e30f;
                if (col + 1 > row0 + 8) sc[t][3] = -1e30f;
            }
        }

        // ---- online softmax --------------------------------------------------
        float r0m = -1e30f, r1m = -1e30f;
#pragma unroll
        for (int t = 0; t < 8; t++) {
            r0m = fmaxf(r0m, fmaxf(sc[t][0], sc[t][1]));
            r1m = fmaxf(r1m, fmaxf(sc[t][2], sc[t][3]));
        }
        r0m = fmaxf(r0m, __shfl_xor_sync(0xffffffffu, r0m, 1));
        r0m = fmaxf(r0m, __shfl_xor_sync(0xffffffffu, r0m, 2));
        r1m = fmaxf(r1m, __shfl_xor_sync(0xffffffffu, r1m, 1));
        r1m = fmaxf(r1m, __shfl_xor_sync(0xffffffffu, r1m, 2));
        float nm0 = fmaxf(m0, r0m), nm1 = fmaxf(m1, r1m);
        float a0 = __expf(m0 - nm0), a1 = __expf(m1 - nm1);

        float s0 = 0.f, s1 = 0.f;
#pragma unroll
        for (int t = 0; t < 8; t++) {
            sc[t][0] = __expf(sc[t][0] - nm0); s0 += sc[t][0];
            sc[t][1] = __expf(sc[t][1] - nm0); s0 += sc[t][1];
            sc[t][2] = __expf(sc[t][2] - nm1); s1 += sc[t][2];
            sc[t][3] = __expf(sc[t][3] - nm1); s1 += sc[t][3];
        }
        s0 += __shfl_xor_sync(0xffffffffu, s0, 1);
        s0 += __shfl_xor_sync(0xffffffffu, s0, 2);
        s1 += __shfl_xor_sync(0xffffffffu, s1, 1);
        s1 += __shfl_xor_sync(0xffffffffu, s1, 2);
        l0 = l0 * a0 + s0;
        l1 = l1 * a1 + s1;
        m0 = nm0; m1 = nm1;
#pragma unroll
        for (int t = 0; t < 16; t++) {
            o[t][0] *= a0; o[t][1] *= a0;
            o[t][2] *= a1; o[t][3] *= a1;
        }

        // ---- O += P V (3-term split, P from registers) ----------------------
#pragma unroll
        for (int g = 0; g < 4; g++) {
            uint32_t aph[4], apl[4];
            split2(sc[2*g][0],   sc[2*g][1],   aph[0], apl[0]);
            split2(sc[2*g][2],   sc[2*g][3],   aph[1], apl[1]);
            split2(sc[2*g+1][0], sc[2*g+1][1], aph[2], apl[2]);
            split2(sc[2*g+1][2], sc[2*g+1][3], aph[3], apl[3]);
#pragma unroll
            for (int n16 = 0; n16 < 8; n16++) {
                uint32_t vaddr = sb + 2 * ATILE
                    + (uint32_t)((g * 16 + (l & 15)) * ASTRIDE
                                 + n16 * 32 + (l >> 4) * 16);
                uint32_t bvh[2][2], bvl[2][2];
                ldm4t(bvh[0][0], bvh[0][1], bvh[1][0], bvh[1][1], vaddr);
                ldm4t(bvl[0][0], bvl[0][1], bvl[1][0], bvl[1][1], vaddr + ATILE);
#pragma unroll
                for (int j = 0; j < 2; j++) {
                    int t = n16 * 2 + j;
                    mma16816(o[t], aph, bvh[j]);
                    mma16816(o[t], apl, bvh[j]);
                    mma16816(o[t], aph, bvl[j]);
                }
            }
        }
        __syncthreads();   // before next kb overwrites K/V tiles
    }

    // ---- write O ------------------------------------------------------------
    float i0 = 1.f / l0, i1 = 1.f / l1;
    const int colb = h * HD + 2 * (l & 3);
#pragma unroll
    for (int t = 0; t < 16; t++) {
        float* p0 = O + (size_t)row0 * (NH * HD) + colb + t * 8;
        float* p1 = O + (size_t)(row0 + 8) * (NH * HD) + colb + t * 8;
        *(float2*)p0 = make_float2(o[t][0] * i0, o[t][1] * i0);
        *(float2*)p1 = make_float2(o[t][2] * i1, o[t][3] * i1);
    }
}

// ---------------- launch ----------------------------------------------------
extern "C" void kernel_launch(void* const* d_in, const int* in_sizes, int n_in,
                              void* d_out, int out_size)
{
    const float* x     = (const float*)d_in[0];
    const float* cosf_ = (const float*)d_in[1];
    const float* sinf_ = (const float*)d_in[2];
    const float* in_ck = (const float*)d_in[5];
    const float* in_cv = (const float*)d_in[6];
    const float* Wqkv  = (const float*)d_in[7];
    const float* Wo    = (const float*)d_in[8];

    float* out     = (float*)d_out;
    float* cache_k = out + (size_t)SEQLEN * DIM;
    float* cache_v = cache_k + (size_t)WIN * KV_ROW;

    float *xqkv_p, *q_p, *attn_p;
    __nv_bfloat16 *xc_p, *attnc_p, *wqkvc_p, *woc_p;
    __nv_bfloat16 *qhi_p, *qlo_p, *khi_p, *klo_p, *vhi_p, *vlo_p;
    cudaGetSymbolAddress((void**)&xqkv_p,  g_xqkv);
    cudaGetSymbolAddress((void**)&q_p,     g_q);
    cudaGetSymbolAddress((void**)&attn_p,  g_attn);
    cudaGetSymbolAddress((void**)&xc_p,    g_xc);
    cudaGetSymbolAddress((void**)&attnc_p, g_attnc);
    cudaGetSymbolAddress((void**)&wqkvc_p, g_wqkvc);
    cudaGetSymbolAddress((void**)&woc_p,   g_woc);
    cudaGetSymbolAddress((void**)&qhi_p,   g_qhi);
    cudaGetSymbolAddress((void**)&qlo_p,   g_qlo);
    cudaGetSymbolAddress((void**)&khi_p,   g_khi);
    cudaGetSymbolAddress((void**)&klo_p,   g_klo);
    cudaGetSymbolAddress((void**)&vhi_p,   g_vhi);
    cudaGetSymbolAddress((void**)&vlo_p,   g_vlo);

    size_t cache_bytes = (size_t)WIN * KV_ROW * sizeof(float);
    cudaMemcpyAsync(cache_k, in_ck, cache_bytes, cudaMemcpyDeviceToDevice, 0);
    cudaMemcpyAsync(cache_v, in_cv, cache_bytes, cudaMemcpyDeviceToDevice, 0);

    cudaFuncSetAttribute(gemm_mma, cudaFuncAttributeMaxDynamicSharedMemorySize,
                         GEMM_SMEM);
    cudaFuncSetAttribute(attn_tc, cudaFuncAttributeMaxDynamicSharedMemorySize,
                         ATTN_SMEM);

    // split-bf16 conversions for GEMM operands
    {
        long long t4;
        t4 = (long long)SEQLEN * DIM / 4;
        convert_split<<<(unsigned)((t4 + 255) / 256), 256>>>(x, xc_p, DIM, 1, t4);
        t4 = (long long)QKV_N * DIM / 4;
        convert_split<<<(unsigned)((t4 + 255) / 256), 256>>>(Wqkv, wqkvc_p, DIM, 0, t4);
        t4 = (long long)DIM * DIM / 4;
        convert_split<<<(unsigned)((t4 + 255) / 256), 256>>>(Wo, woc_p, DIM, 0, t4);
    }

    // 1) QKV projection (tensor cores)
    gemm_mma<<<dim3(QKV_N / 128, SEQLEN / 128), 256, GEMM_SMEM>>>(
        xc_p, wqkvc_p, xqkv_p, QKV_N);

    // 2) RoPE + cache writes
    rope_kernel<<<SEQLEN, 256>>>(xqkv_p, cosf_, sinf_, q_p, cache_k, cache_v);

    // 3) split q/k/v to bf16 hi/lo, head-major
    qsplit<<<SEQLEN, 256>>>(q_p, qhi_p, qlo_p);
    kvsplit<<<SEQLEN, 256>>>(cache_k, cache_v, khi_p, klo_p, vhi_p, vlo_p);

    // 4) tensor-core causal flash attention
    attn_tc<<<dim3(SEQLEN / 128, NH), 256, ATTN_SMEM>>>(
        qhi_p, qlo_p, khi_p, klo_p, vhi_p, vlo_p, attn_p);

    // 5) output projection (tensor cores)
    {
        long long t4 = (long long)SEQLEN * DIM / 4;
        convert_split<<<(unsigned)((t4 + 255) / 256), 256>>>(attn_p, attnc_p, DIM, 1, t4);
    }
    gemm_mma<<<dim3(DIM / 128, SEQLEN / 128), 256, GEMM_SMEM>>>(
        attnc_p, woc_p, out, DIM);
}